// round 15
// baseline (speedup 1.0000x reference)
#include <cuda_runtime.h>
#include <cuda_fp16.h>
#include <stdint.h>

#define BATCH 4
#define SEQ   2048
#define DIM   1024
#define NH    16
#define HD    64
#define MTOT  (BATCH*SEQ)
// scale*log2(e): folded into q so 2^score = exp(0.125*qk)
#define QSCALE 0.1803368801111204f

// ---- scratch ----
__device__ __half g_q[MTOT * DIM];
__device__ __half g_k[MTOT * DIM];
__device__ __half g_v[MTOT * DIM];    // [b*S+s][n]  (temp)
__device__ __half g_vT[MTOT * DIM];   // [(b*NH+h)*HD+d][s]
__device__ __half g_ctx[MTOT * DIM];
__device__ __half g_x[MTOT * DIM];
__device__ __half g_w[4 * DIM * DIM]; // W^T, [n][k]
__device__ __half g_r[(size_t)BATCH * SEQ * SEQ];  // 1/Z, fp16

// ---- helpers ----
__device__ __forceinline__ uint32_t h2u(float a, float b) {
    __half2 h = __floats2half2_rn(a, b);
    return *(uint32_t*)&h;
}
__device__ __forceinline__ void mma16(float c[4], const uint32_t a[4], const uint32_t b[2]) {
    asm volatile(
        "mma.sync.aligned.m16n8k16.row.col.f32.f16.f16.f32 "
        "{%0,%1,%2,%3}, {%4,%5,%6,%7}, {%8,%9}, {%0,%1,%2,%3};\n"
        : "+f"(c[0]), "+f"(c[1]), "+f"(c[2]), "+f"(c[3])
        : "r"(a[0]), "r"(a[1]), "r"(a[2]), "r"(a[3]), "r"(b[0]), "r"(b[1]));
}
// fp16 accumulator variant: C fragment = 2 x half2 (row g, row g+8)
__device__ __forceinline__ void mma16h(uint32_t c[2], const uint32_t a[4], const uint32_t b[2]) {
    asm volatile(
        "mma.sync.aligned.m16n8k16.row.col.f16.f16.f16.f16 "
        "{%0,%1}, {%2,%3,%4,%5}, {%6,%7}, {%0,%1};\n"
        : "+r"(c[0]), "+r"(c[1])
        : "r"(a[0]), "r"(a[1]), "r"(a[2]), "r"(a[3]), "r"(b[0]), "r"(b[1]));
}
__device__ __forceinline__ void ldsm4(uint32_t r[4], const uint32_t* p) {
    uint32_t a = (uint32_t)__cvta_generic_to_shared(p);
    asm volatile("ldmatrix.sync.aligned.m8n8.x4.shared.b16 {%0,%1,%2,%3}, [%4];\n"
                 : "=r"(r[0]), "=r"(r[1]), "=r"(r[2]), "=r"(r[3]) : "r"(a));
}
__device__ __forceinline__ void cpa16(void* s, const void* g) {
    uint32_t sa = (uint32_t)__cvta_generic_to_shared(s);
    asm volatile("cp.async.ca.shared.global [%0], [%1], 16;\n" ::"r"(sa), "l"(g));
}
__device__ __forceinline__ void cp_commit() { asm volatile("cp.async.commit_group;\n"); }
template <int N>
__device__ __forceinline__ void cp_wait() { asm volatile("cp.async.wait_group %0;\n" ::"n"(N)); }

// =====================================================================
// x -> fp16
// =====================================================================
__global__ void round_x_h(const float* __restrict__ x) {
    const int n4 = MTOT * DIM / 4;
    uint2* out = (uint2*)g_x;
    int i = blockIdx.x * blockDim.x + threadIdx.x;
    int stride = gridDim.x * blockDim.x;
    for (; i < n4; i += stride) {
        float4 v = ((const float4*)x)[i];
        uint2 o;
        o.x = h2u(v.x, v.y);
        o.y = h2u(v.z, v.w);
        out[i] = o;
    }
}

// =====================================================================
// weights -> fp16, transposed to [n][k]
// =====================================================================
__global__ void round_w_t(const float* __restrict__ w0, const float* __restrict__ w1,
                          const float* __restrict__ w2, const float* __restrict__ w3) {
    __shared__ float t[32][33];
    const float* src = (blockIdx.z == 0) ? w0 : (blockIdx.z == 1) ? w1 : (blockIdx.z == 2) ? w2 : w3;
    __half* dst = g_w + (size_t)blockIdx.z * DIM * DIM;
    const int k0 = blockIdx.y * 32, n0 = blockIdx.x * 32;
    const int r = threadIdx.x >> 5, cc = threadIdx.x & 31;
#pragma unroll
    for (int i = 0; i < 4; i++) t[r + i * 8][cc] = src[(size_t)(k0 + r + i * 8) * DIM + n0 + cc];
    __syncthreads();
#pragma unroll
    for (int i = 0; i < 4; i++)
        dst[(size_t)(n0 + r + i * 8) * DIM + k0 + cc] = __float2half_rn(t[cc][r + i * 8]);
}

// =====================================================================
// v [s][n] -> vT [n][s], per batch
// =====================================================================
__global__ void transpose_v() {
    __shared__ __half t[32][33];
    const int b = blockIdx.z, s0 = blockIdx.x * 32, n0 = blockIdx.y * 32;
    const int r = threadIdx.x >> 5, cc = threadIdx.x & 31;
#pragma unroll
    for (int i = 0; i < 4; i++)
        t[r + i * 8][cc] = g_v[(size_t)(b * SEQ + s0 + r + i * 8) * DIM + n0 + cc];
    __syncthreads();
#pragma unroll
    for (int i = 0; i < 4; i++)
        g_vT[((size_t)b * DIM + n0 + r + i * 8) * SEQ + s0 + cc] = t[cc][r + i * 8];
}

// =====================================================================
// GEMM body (fp32 acc): C[M,1024] = (A @ W) * out_scale
// Block 128x256, k-stage 64, 8 warps (2m x 4n), warp 64x64, GS=3, LDSM.
// =====================================================================
#define GS 3
#define GA_W (128 * 36)
#define GB_W (256 * 36)
#define G_SMEM (GS * (GA_W + GB_W) * 4)

__device__ __forceinline__ void gemm_body(const __half* __restrict__ A,
                                          const __half* __restrict__ WT,
                                          void* __restrict__ Cout, int half_out,
                                          float out_scale, int bx, int by) {
    extern __shared__ uint32_t smu[];
    uint32_t* sA = smu;
    uint32_t* sB = smu + GS * GA_W;
    const int tid = threadIdx.x;
    const int m0 = by * 128, n0 = bx * 256;
    const int w = tid >> 5, lane = tid & 31, g = lane >> 2, tg = lane & 3;
    const int wm = (w >> 2) * 64, wn = (w & 3) * 64;
    const int lrA = (lane & 7) + ((lane >> 3) & 1) * 8, lcA = (lane >> 4) * 4;
    const int lrB = (lane & 7) + (lane >> 4) * 8, lcB = ((lane >> 3) & 1) * 4;

    float acc[4][8][4]{};

    auto load_tile = [&](int st, int kt) {
        uint32_t* a = sA + st * GA_W;
        uint32_t* bb = sB + st * GB_W;
#pragma unroll
        for (int i = 0; i < 4; i++) {
            int c = tid + 256 * i;
            int r = c >> 3, cw = (c & 7) * 4;
            cpa16(a + r * 36 + cw, A + (size_t)(m0 + r) * DIM + kt + cw * 2);
        }
#pragma unroll
        for (int i = 0; i < 8; i++) {
            int c = tid + 256 * i;
            int r = c >> 3, cw = (c & 7) * 4;
            cpa16(bb + r * 36 + cw, WT + (size_t)(n0 + r) * DIM + kt + cw * 2);
        }
    };

    const int NK = DIM / 64;  // 16
#pragma unroll
    for (int s = 0; s < GS - 1; s++) {
        load_tile(s, s * 64);
        cp_commit();
    }
    for (int t = 0; t < NK; t++) {
        cp_wait<GS - 2>();
        __syncthreads();
        int ld = t + GS - 1;
        if (ld < NK) load_tile(ld % GS, ld * 64);
        cp_commit();
        const uint32_t* a = sA + (t % GS) * GA_W;
        const uint32_t* b = sB + (t % GS) * GB_W;
#pragma unroll
        for (int kw = 0; kw < 32; kw += 8) {
            uint32_t af[4][4], bf[8][2];
#pragma unroll
            for (int mt = 0; mt < 4; mt++)
                ldsm4(af[mt], a + (wm + mt * 16 + lrA) * 36 + kw + lcA);
#pragma unroll
            for (int np = 0; np < 4; np++) {
                uint32_t tmp[4];
                ldsm4(tmp, b + (wn + np * 16 + lrB) * 36 + kw + lcB);
                bf[2 * np][0] = tmp[0];
                bf[2 * np][1] = tmp[1];
                bf[2 * np + 1][0] = tmp[2];
                bf[2 * np + 1][1] = tmp[3];
            }
#pragma unroll
            for (int mt = 0; mt < 4; mt++)
#pragma unroll
                for (int nt = 0; nt < 8; nt++) mma16(acc[mt][nt], af[mt], bf[nt]);
        }
    }
#pragma unroll
    for (int mt = 0; mt < 4; mt++)
#pragma unroll
        for (int nt = 0; nt < 8; nt++) {
            int row = m0 + wm + mt * 16 + g;
            int col = n0 + wn + nt * 8 + 2 * tg;
            if (half_out) {
                __half* C = (__half*)Cout;
                *(uint32_t*)(C + (size_t)row * DIM + col) =
                    h2u(acc[mt][nt][0] * out_scale, acc[mt][nt][1] * out_scale);
                *(uint32_t*)(C + (size_t)(row + 8) * DIM + col) =
                    h2u(acc[mt][nt][2] * out_scale, acc[mt][nt][3] * out_scale);
            } else {
                float* C = (float*)Cout;
                *(float2*)(C + (size_t)row * DIM + col) = make_float2(acc[mt][nt][0], acc[mt][nt][1]);
                *(float2*)(C + (size_t)(row + 8) * DIM + col) = make_float2(acc[mt][nt][2], acc[mt][nt][3]);
            }
        }
}

__global__ __launch_bounds__(256) void gemm_fp16(const __half* __restrict__ A,
                                                 const __half* __restrict__ WT,
                                                 void* __restrict__ Cout, int half_out,
                                                 float out_scale) {
    gemm_body(A, WT, Cout, half_out, out_scale, blockIdx.x, blockIdx.y);
}

// fused q/k/v projections: grid.z selects weight / destination / scale
__global__ __launch_bounds__(256) void gemm_qkv(const __half* __restrict__ A) {
    const int z = blockIdx.z;
    const __half* WT = g_w + (size_t)z * DIM * DIM;
    __half* dst = (z == 0) ? g_q : (z == 1) ? g_k : g_v;
    float sc = (z == 0) ? QSCALE : 1.0f;
    gemm_body(A, WT, dst, 1, sc, blockIdx.x, blockIdx.y);
}

// =====================================================================
// Pass A: R = 1 / sum_h 2^(q.k)   (q pre-scaled by scale*log2e)
// fp16 MMA with fp16 accumulator (C frags feed h2exp2 directly).
// =====================================================================
#define ZT_W (128 * 36)
#define Z_SMEM (4 * ZT_W * 4)

__global__ __launch_bounds__(256) void attn_z() {
    extern __shared__ uint32_t smu[];
    uint32_t* sQ = smu;
    uint32_t* sK = smu + 2 * ZT_W;
    const int tid = threadIdx.x;
    const int b = blockIdx.z, qt = blockIdx.y * 128, kt = blockIdx.x * 128;
    const int w = tid >> 5, lane = tid & 31, g = lane >> 2, tg = lane & 3;
    const int wm = (w >> 2) * 64, wn = (w & 3) * 32;
    const int lrA = (lane & 7) + ((lane >> 3) & 1) * 8, lcA = (lane >> 4) * 4;
    const int lrB = (lane & 7) + (lane >> 4) * 8, lcB = ((lane >> 3) & 1) * 4;

    const __half* qb = g_q + (size_t)(b * SEQ + qt) * DIM;
    const __half* kb = g_k + (size_t)(b * SEQ + kt) * DIM;

    auto load_head = [&](int st, int h) {
        uint32_t* q = sQ + st * ZT_W;
        uint32_t* k = sK + st * ZT_W;
#pragma unroll
        for (int i = 0; i < 4; i++) {
            int c = tid + 256 * i;
            int r = c >> 3, cw = (c & 7) * 4;
            cpa16(q + r * 36 + cw, qb + (size_t)r * DIM + h * HD + cw * 2);
            cpa16(k + r * 36 + cw, kb + (size_t)r * DIM + h * HD + cw * 2);
        }
    };

    float zacc[4][4][4]{};
    load_head(0, 0);
    cp_commit();

    for (int h = 0; h < NH; h++) {
        cp_wait<0>();
        __syncthreads();
        if (h + 1 < NH) load_head((h + 1) & 1, h + 1);
        cp_commit();
        const uint32_t* q = sQ + (h & 1) * ZT_W;
        const uint32_t* k = sK + (h & 1) * ZT_W;

        uint32_t sacc[4][4][2]{};  // fp16 accumulators (half2 row g / row g+8)
#pragma unroll
        for (int kw = 0; kw < 32; kw += 8) {
            uint32_t af[4][4], bf[4][2];
#pragma unroll
            for (int mt = 0; mt < 4; mt++)
                ldsm4(af[mt], q + (wm + mt * 16 + lrA) * 36 + kw + lcA);
#pragma unroll
            for (int np = 0; np < 2; np++) {
                uint32_t tmp[4];
                ldsm4(tmp, k + (wn + np * 16 + lrB) * 36 + kw + lcB);
                bf[2 * np][0] = tmp[0];
                bf[2 * np][1] = tmp[1];
                bf[2 * np + 1][0] = tmp[2];
                bf[2 * np + 1][1] = tmp[3];
            }
#pragma unroll
            for (int mt = 0; mt < 4; mt++)
#pragma unroll
                for (int nt = 0; nt < 4; nt++) mma16h(sacc[mt][nt], af[mt], bf[nt]);
        }
        // zacc += 2^sacc : C frags are already half2 -> h2exp2 directly
#pragma unroll
        for (int i = 0; i < 4; i++)
#pragma unroll
            for (int j = 0; j < 4; j++) {
                float2 e0 = __half22float2(h2exp2(*(__half2*)&sacc[i][j][0]));
                float2 e1 = __half22float2(h2exp2(*(__half2*)&sacc[i][j][1]));
                zacc[i][j][0] += e0.x;
                zacc[i][j][1] += e0.y;
                zacc[i][j][2] += e1.x;
                zacc[i][j][3] += e1.y;
            }
    }
#pragma unroll
    for (int mt = 0; mt < 4; mt++)
#pragma unroll
        for (int nt = 0; nt < 4; nt++) {
            int row = qt + wm + mt * 16 + g;
            int col = kt + wn + nt * 8 + 2 * tg;
            __half* rp = g_r + ((size_t)b * SEQ + row) * SEQ + col;
            *(uint32_t*)rp = h2u(1.f / zacc[mt][nt][0], 1.f / zacc[mt][nt][1]);
            *(uint32_t*)(rp + (size_t)8 * SEQ) = h2u(1.f / zacc[mt][nt][2], 1.f / zacc[mt][nt][3]);
        }
}

// =====================================================================
// Pass B: ctx = sum_k 2^(q.k) * R * V   (fp16-acc GEMM1, fragment reuse,
// GEMM2 DEFERRED one tile: GEMM1(t) -> GEMM2(t-1) -> exp(t)->pa.
// exp latency hides under next tile's work. V 4-slot, K/R 2-slot.
// =====================================================================
#define CQ_W (128 * 36)
#define CVT_W (64 * 68)
#define CR_W (128 * 68)
// sQ | sK[2] | sV[4] | sR[2]
#define C_SMEM ((3 * CQ_W + 4 * CVT_W + 2 * CR_W) * 4)

__global__ __launch_bounds__(256) void attn_ctx() {
    extern __shared__ uint32_t smu[];
    uint32_t* sQ = smu;
    uint32_t* sK = smu + CQ_W;                  // 2 slots
    uint32_t* sV = smu + 3 * CQ_W;              // 4 slots
    uint32_t* sR = smu + 3 * CQ_W + 4 * CVT_W;  // 2 slots

    const int tid = threadIdx.x;
    const int b = blockIdx.z, h = blockIdx.x, qt = blockIdx.y * 128;
    const int w = tid >> 5, lane = tid & 31, g = lane >> 2, tg = lane & 3;
    const int wm = (w >> 2) * 64, wn = (w & 3) * 32;
    const int lrA = (lane & 7) + ((lane >> 3) & 1) * 8, lcA = (lane >> 4) * 4;
    const int lrB = (lane & 7) + (lane >> 4) * 8, lcB = ((lane >> 3) & 1) * 4;

    const int NT = SEQ / 128;
    const int kwBase = wn >> 1;

    auto load_kvr = [&](int t) {
        const __half* kb = g_k + (size_t)(b * SEQ + t * 128) * DIM + h * HD;
        uint32_t* kd = sK + (t & 1) * CQ_W;
#pragma unroll
        for (int i = 0; i < 4; i++) {
            int c = tid + 256 * i;
            int r = c >> 3, cw = (c & 7) * 4;
            cpa16(kd + r * 36 + cw, kb + (size_t)r * DIM + cw * 2);
        }
        const __half* vtb = g_vT + ((size_t)(b * NH + h) * HD) * SEQ + t * 128;
        uint32_t* vd = sV + (t & 3) * CVT_W;
#pragma unroll
        for (int i = 0; i < 4; i++) {
            int c = tid + 256 * i;
            int r = c >> 4, cw = (c & 15) * 4;
            cpa16(vd + r * 68 + cw, vtb + (size_t)r * SEQ + cw * 2);
        }
        const __half* rb = g_r + ((size_t)b * SEQ + qt) * SEQ + t * 128;
        __half* rd = (__half*)(sR + (t & 1) * CR_W);
#pragma unroll
        for (int i = 0; i < 8; i++) {
            int c = tid + 256 * i;
            int r = c >> 4, ch = (c & 15) * 8;
            cpa16(rd + r * 136 + ch, rb + (size_t)r * SEQ + ch);
        }
    };

    {
        const __half* qb = g_q + (size_t)(b * SEQ + qt) * DIM + h * HD;
#pragma unroll
        for (int i = 0; i < 4; i++) {
            int c = tid + 256 * i;
            int r = c >> 3, cw = (c & 7) * 4;
            cpa16(sQ + r * 36 + cw, qb + (size_t)r * DIM + cw * 2);
        }
        load_kvr(0);
        cp_commit();
        load_kvr(1);
        cp_commit();
    }

    float cacc[4][8][4]{};
    uint32_t pa[4][2][4];  // P fragments of tile t-1 (A-operand for deferred GEMM2)

    auto do_gemm2 = [&](const uint32_t* vslot) {
#pragma unroll
        for (int kb = 0; kb < 2; kb++) {
            uint32_t bf[8][2];
#pragma unroll
            for (int np = 0; np < 4; np++) {
                uint32_t tmp[4];
                ldsm4(tmp, vslot + (np * 16 + lrB) * 68 + kwBase + kb * 8 + lcB);
                bf[2 * np][0] = tmp[0];
                bf[2 * np][1] = tmp[1];
                bf[2 * np + 1][0] = tmp[2];
                bf[2 * np + 1][1] = tmp[3];
            }
#pragma unroll
            for (int mt = 0; mt < 4; mt++)
#pragma unroll
                for (int nt = 0; nt < 8; nt++) mma16(cacc[mt][nt], pa[mt][kb], bf[nt]);
        }
    };

    for (int t = 0; t < NT; t++) {
        cp_wait<1>();
        __syncthreads();

        // GEMM1 (fp16 acc): S = Q @ K^T, log2-domain scores
        const uint32_t* kc = sK + (t & 1) * CQ_W;
        uint32_t sacc[4][4][2]{};
#pragma unroll
        for (int kw = 0; kw < 32; kw += 8) {
            uint32_t af[4][4], bf[4][2];
#pragma unroll
            for (int mt = 0; mt < 4; mt++)
                ldsm4(af[mt], sQ + (wm + mt * 16 + lrA) * 36 + kw + lcA);
#pragma unroll
            for (int np = 0; np < 2; np++) {
                uint32_t tmp[4];
                ldsm4(tmp, kc + (wn + np * 16 + lrB) * 36 + kw + lcB);
                bf[2 * np][0] = tmp[0];
                bf[2 * np][1] = tmp[1];
                bf[2 * np + 1][0] = tmp[2];
                bf[2 * np + 1][1] = tmp[3];
            }
#pragma unroll
            for (int mt = 0; mt < 4; mt++)
#pragma unroll
                for (int nt = 0; nt < 4; nt++) mma16h(sacc[mt][nt], af[mt], bf[nt]);
        }

        // Deferred GEMM2 for tile t-1 (independent of this tile's exp)
        if (t > 0) do_gemm2(sV + ((t - 1) & 3) * CVT_W);

        // exp/pa for tile t (consumed next iteration -> latency hidden)
        const __half* rslot = (const __half*)(sR + (t & 1) * CR_W);
#pragma unroll
        for (int mt = 0; mt < 4; mt++)
#pragma unroll
            for (int kb = 0; kb < 2; kb++) {
                int row = wm + mt * 16 + g;
                int col = wn + (2 * kb) * 8 + 2 * tg;
                __half2 r0 = *(__half2*)(rslot + row * 136 + col);
                __half2 r1 = *(__half2*)(rslot + (row + 8) * 136 + col);
                __half2 r2 = *(__half2*)(rslot + row * 136 + col + 8);
                __half2 r3 = *(__half2*)(rslot + (row + 8) * 136 + col + 8);
                int lo = 2 * kb, hi = 2 * kb + 1;
                __half2 p0 = __hmul2(h2exp2(*(__half2*)&sacc[mt][lo][0]), r0);
                __half2 p1 = __hmul2(h2exp2(*(__half2*)&sacc[mt][lo][1]), r1);
                __half2 p2 = __hmul2(h2exp2(*(__half2*)&sacc[mt][hi][0]), r2);
                __half2 p3 = __hmul2(h2exp2(*(__half2*)&sacc[mt][hi][1]), r3);
                pa[mt][kb][0] = *(uint32_t*)&p0;
                pa[mt][kb][1] = *(uint32_t*)&p1;
                pa[mt][kb][2] = *(uint32_t*)&p2;
                pa[mt][kb][3] = *(uint32_t*)&p3;
            }
        __syncthreads();

        if (t + 2 < NT) load_kvr(t + 2);
        cp_commit();
    }
    // tail: GEMM2 for the final tile
    do_gemm2(sV + ((NT - 1) & 3) * CVT_W);
    __syncthreads();

    // 4-way k-slice reduction via sR (free now)
    float* red = (float*)sR;
    const int ks = w & 3, mg = w >> 2;
    float* rbase = red + mg * 64 * 68;
#pragma unroll
    for (int s = 1; s < 4; s++) {
        if (ks == s) {
#pragma unroll
            for (int mt = 0; mt < 4; mt++)
#pragma unroll
                for (int nt = 0; nt < 8; nt++) {
                    int row = mt * 16 + g;
                    int col = nt * 8 + 2 * tg;
                    if (s == 1) {
                        *(float2*)&rbase[row * 68 + col] = make_float2(cacc[mt][nt][0], cacc[mt][nt][1]);
                        *(float2*)&rbase[(row + 8) * 68 + col] = make_float2(cacc[mt][nt][2], cacc[mt][nt][3]);
                    } else {
                        float2 a0 = *(float2*)&rbase[row * 68 + col];
                        float2 a1 = *(float2*)&rbase[(row + 8) * 68 + col];
                        a0.x += cacc[mt][nt][0];
                        a0.y += cacc[mt][nt][1];
                        a1.x += cacc[mt][nt][2];
                        a1.y += cacc[mt][nt][3];
                        *(float2*)&rbase[row * 68 + col] = a0;
                        *(float2*)&rbase[(row + 8) * 68 + col] = a1;
                    }
                }
        }
        __syncthreads();
    }
    if (ks == 0) {
        __half* cb = g_ctx + (size_t)(b * SEQ + qt) * DIM + h * HD;
#pragma unroll
        for (int mt = 0; mt < 4; mt++)
#pragma unroll
            for (int nt = 0; nt < 8; nt++) {
                int row = mt * 16 + g;
                int col = nt * 8 + 2 * tg;
                float2 o0 = *(float2*)&rbase[row * 68 + col];
                float2 o1 = *(float2*)&rbase[(row + 8) * 68 + col];
                *(uint32_t*)(cb + (size_t)(wm + row) * DIM + col) =
                    h2u(o0.x + cacc[mt][nt][0], o0.y + cacc[mt][nt][1]);
                *(uint32_t*)(cb + (size_t)(wm + row + 8) * DIM + col) =
                    h2u(o1.x + cacc[mt][nt][2], o1.y + cacc[mt][nt][3]);
            }
    }
}

// =====================================================================
extern "C" void kernel_launch(void* const* d_in, const int* in_sizes, int n_in,
                              void* d_out, int out_size) {
    const float* x = (const float*)d_in[0];
    const float* wq = (const float*)d_in[1];
    const float* wk = (const float*)d_in[2];
    const float* wv = (const float*)d_in[3];
    const float* wo = (const float*)d_in[4];
    float* out = (float*)d_out;

    __half *ctx, *xr, *wr;
    cudaGetSymbolAddress((void**)&ctx, g_ctx);
    cudaGetSymbolAddress((void**)&xr, g_x);
    cudaGetSymbolAddress((void**)&wr, g_w);

    static int attr_done = 0;
    if (!attr_done) {
        cudaFuncSetAttribute(gemm_fp16, cudaFuncAttributeMaxDynamicSharedMemorySize, G_SMEM);
        cudaFuncSetAttribute(gemm_qkv, cudaFuncAttributeMaxDynamicSharedMemorySize, G_SMEM);
        cudaFuncSetAttribute(attn_z, cudaFuncAttributeMaxDynamicSharedMemorySize, Z_SMEM);
        cudaFuncSetAttribute(attn_ctx, cudaFuncAttributeMaxDynamicSharedMemorySize, C_SMEM);
        attr_done = 1;
    }

    round_x_h<<<2048, 256>>>(x);
    round_w_t<<<dim3(32, 32, 4), 256>>>(wq, wk, wv, wo);

    gemm_qkv<<<dim3(DIM / 256, MTOT / 128, 3), 256, G_SMEM>>>(xr);

    transpose_v<<<dim3(SEQ / 32, DIM / 32, BATCH), 256>>>();

    attn_z<<<dim3(SEQ / 128, SEQ / 128, BATCH), 256, Z_SMEM>>>();

    attn_ctx<<<dim3(NH, SEQ / 128, BATCH), 256, C_SMEM>>>();

    gemm_fp16<<<dim3(DIM / 256, MTOT / 128), 256, G_SMEM>>>(ctx, wr + 3 * DIM * DIM, out, 0, 1.0f);
}

// round 16
// speedup vs baseline: 1.0273x; 1.0273x over previous
#include <cuda_runtime.h>
#include <cuda_fp16.h>
#include <stdint.h>

#define BATCH 4
#define SEQ   2048
#define DIM   1024
#define NH    16
#define HD    64
#define MTOT  (BATCH*SEQ)
// scale*log2(e): folded into q so 2^score = exp(0.125*qk)
#define QSCALE 0.1803368801111204f

// ---- scratch ----
__device__ __half g_q[MTOT * DIM];
__device__ __half g_k[MTOT * DIM];
__device__ __half g_v[MTOT * DIM];    // [b*S+s][n]  (temp)
__device__ __half g_vT[MTOT * DIM];   // [(b*NH+h)*HD+d][s]
__device__ __half g_ctx[MTOT * DIM];
__device__ __half g_x[MTOT * DIM];
__device__ __half g_w[4 * DIM * DIM]; // W^T, [n][k]
__device__ __half g_r[(size_t)BATCH * SEQ * SEQ];  // 1/Z, fp16

// ---- helpers ----
__device__ __forceinline__ uint32_t h2u(float a, float b) {
    __half2 h = __floats2half2_rn(a, b);
    return *(uint32_t*)&h;
}
__device__ __forceinline__ void mma16(float c[4], const uint32_t a[4], const uint32_t b[2]) {
    asm volatile(
        "mma.sync.aligned.m16n8k16.row.col.f32.f16.f16.f32 "
        "{%0,%1,%2,%3}, {%4,%5,%6,%7}, {%8,%9}, {%0,%1,%2,%3};\n"
        : "+f"(c[0]), "+f"(c[1]), "+f"(c[2]), "+f"(c[3])
        : "r"(a[0]), "r"(a[1]), "r"(a[2]), "r"(a[3]), "r"(b[0]), "r"(b[1]));
}
// fp16 accumulator variant: C fragment = 2 x half2 (row g, row g+8)
__device__ __forceinline__ void mma16h(uint32_t c[2], const uint32_t a[4], const uint32_t b[2]) {
    asm volatile(
        "mma.sync.aligned.m16n8k16.row.col.f16.f16.f16.f16 "
        "{%0,%1}, {%2,%3,%4,%5}, {%6,%7}, {%0,%1};\n"
        : "+r"(c[0]), "+r"(c[1])
        : "r"(a[0]), "r"(a[1]), "r"(a[2]), "r"(a[3]), "r"(b[0]), "r"(b[1]));
}
__device__ __forceinline__ void ldsm4(uint32_t r[4], const uint32_t* p) {
    uint32_t a = (uint32_t)__cvta_generic_to_shared(p);
    asm volatile("ldmatrix.sync.aligned.m8n8.x4.shared.b16 {%0,%1,%2,%3}, [%4];\n"
                 : "=r"(r[0]), "=r"(r[1]), "=r"(r[2]), "=r"(r[3]) : "r"(a));
}
__device__ __forceinline__ void cpa16(void* s, const void* g) {
    uint32_t sa = (uint32_t)__cvta_generic_to_shared(s);
    asm volatile("cp.async.ca.shared.global [%0], [%1], 16;\n" ::"r"(sa), "l"(g));
}
__device__ __forceinline__ void cp_commit() { asm volatile("cp.async.commit_group;\n"); }
template <int N>
__device__ __forceinline__ void cp_wait() { asm volatile("cp.async.wait_group %0;\n" ::"n"(N)); }

// =====================================================================
// Fused pre-rounding: z 0-1 = x halves -> g_x ; z 2-5 = weights -> g_w (W^T)
// =====================================================================
__global__ void round_all(const float* __restrict__ x,
                          const float* __restrict__ w0, const float* __restrict__ w1,
                          const float* __restrict__ w2, const float* __restrict__ w3) {
    const int z = blockIdx.z;
    if (z < 2) {
        const int n4 = MTOT * DIM / 8;  // per half
        const float4* in = (const float4*)x + (size_t)z * n4;
        uint2* out = (uint2*)g_x + (size_t)z * n4;
        int i = blockIdx.x * blockDim.x + threadIdx.x;
        int stride = gridDim.x * blockDim.x;
        for (; i < n4; i += stride) {
            float4 v = in[i];
            uint2 o;
            o.x = h2u(v.x, v.y);
            o.y = h2u(v.z, v.w);
            out[i] = o;
        }
    } else {
        __shared__ float t[32][33];
        const int wz = z - 2;
        const float* src = (wz == 0) ? w0 : (wz == 1) ? w1 : (wz == 2) ? w2 : w3;
        __half* dst = g_w + (size_t)wz * DIM * DIM;
        // blockIdx.x encodes (n-tile, k-tile): 32x32 tiles => 32*32 = 1024 blocks
        const int k0 = (blockIdx.x & 31) * 32, n0 = (blockIdx.x >> 5) * 32;
        const int r = threadIdx.x >> 5, cc = threadIdx.x & 31;
#pragma unroll
        for (int i = 0; i < 4; i++) t[r + i * 8][cc] = src[(size_t)(k0 + r + i * 8) * DIM + n0 + cc];
        __syncthreads();
#pragma unroll
        for (int i = 0; i < 4; i++)
            dst[(size_t)(n0 + r + i * 8) * DIM + k0 + cc] = __float2half_rn(t[cc][r + i * 8]);
    }
}

// =====================================================================
// v [s][n] -> vT [n][s], 64x64 tiles, uint2-granularity smem staging
// =====================================================================
__global__ void transpose_v() {
    __shared__ __half t[64][65];
    const int b = blockIdx.z, s0 = blockIdx.x * 64, n0 = blockIdx.y * 64;
    const int r = threadIdx.x >> 4, cc = (threadIdx.x & 15) * 4;  // 16 rows x 64 cols per pass
#pragma unroll
    for (int i = 0; i < 4; i++) {
        const __half* src = g_v + (size_t)(b * SEQ + s0 + r + i * 16) * DIM + n0 + cc;
        *(uint2*)&t[r + i * 16][cc] = *(const uint2*)src;
    }
    __syncthreads();
#pragma unroll
    for (int i = 0; i < 4; i++) {
        __half tmp[4];
#pragma unroll
        for (int j = 0; j < 4; j++) tmp[j] = t[cc + j][r + i * 16];
        *(uint2*)(g_vT + ((size_t)b * DIM + n0 + cc) * SEQ + s0 + r + i * 16) = *(uint2*)tmp;
    }
}
// NOTE: the write above is wrong granularity (4 halves along n, same s) — use safe variant:
__global__ void transpose_v64() {
    __shared__ __half t[64][72];
    const int b = blockIdx.z, s0 = blockIdx.x * 64, n0 = blockIdx.y * 64;
    const int tid = threadIdx.x;
    // load 64x64 tile: 256 threads, 16 rows/pass via uint2 (4 halves)
    const int lr = tid >> 4, lc = (tid & 15) * 4;
#pragma unroll
    for (int i = 0; i < 4; i++)
        *(uint2*)&t[lr + i * 16][lc] = *(const uint2*)(g_v + (size_t)(b * SEQ + s0 + lr + i * 16) * DIM + n0 + lc);
    __syncthreads();
    // store transposed: row of output = n, cols = s; gather 4 s-values per thread
#pragma unroll
    for (int i = 0; i < 4; i++) {
        int n = lr + i * 16;       // output row (n)
        int s = lc;                // output col base (s)
        __half tmp[4];
#pragma unroll
        for (int j = 0; j < 4; j++) tmp[j] = t[s + j][n];
        *(uint2*)(g_vT + ((size_t)b * DIM + n0 + n) * SEQ + s0 + s) = *(uint2*)tmp;
    }
}

// =====================================================================
// GEMM body (fp32 acc): C[M,1024] = (A @ W) * out_scale
// Block 128x256, k-stage 64, 8 warps (2m x 4n), warp 64x64, GS=3, LDSM.
// =====================================================================
#define GS 3
#define GA_W (128 * 36)
#define GB_W (256 * 36)
#define G_SMEM (GS * (GA_W + GB_W) * 4)

__device__ __forceinline__ void gemm_body(const __half* __restrict__ A,
                                          const __half* __restrict__ WT,
                                          void* __restrict__ Cout, int half_out,
                                          float out_scale, int bx, int by) {
    extern __shared__ uint32_t smu[];
    uint32_t* sA = smu;
    uint32_t* sB = smu + GS * GA_W;
    const int tid = threadIdx.x;
    const int m0 = by * 128, n0 = bx * 256;
    const int w = tid >> 5, lane = tid & 31, g = lane >> 2, tg = lane & 3;
    const int wm = (w >> 2) * 64, wn = (w & 3) * 64;
    const int lrA = (lane & 7) + ((lane >> 3) & 1) * 8, lcA = (lane >> 4) * 4;
    const int lrB = (lane & 7) + (lane >> 4) * 8, lcB = ((lane >> 3) & 1) * 4;

    float acc[4][8][4]{};

    auto load_tile = [&](int st, int kt) {
        uint32_t* a = sA + st * GA_W;
        uint32_t* bb = sB + st * GB_W;
#pragma unroll
        for (int i = 0; i < 4; i++) {
            int c = tid + 256 * i;
            int r = c >> 3, cw = (c & 7) * 4;
            cpa16(a + r * 36 + cw, A + (size_t)(m0 + r) * DIM + kt + cw * 2);
        }
#pragma unroll
        for (int i = 0; i < 8; i++) {
            int c = tid + 256 * i;
            int r = c >> 3, cw = (c & 7) * 4;
            cpa16(bb + r * 36 + cw, WT + (size_t)(n0 + r) * DIM + kt + cw * 2);
        }
    };

    const int NK = DIM / 64;  // 16
#pragma unroll
    for (int s = 0; s < GS - 1; s++) {
        load_tile(s, s * 64);
        cp_commit();
    }
    for (int t = 0; t < NK; t++) {
        cp_wait<GS - 2>();
        __syncthreads();
        int ld = t + GS - 1;
        if (ld < NK) load_tile(ld % GS, ld * 64);
        cp_commit();
        const uint32_t* a = sA + (t % GS) * GA_W;
        const uint32_t* b = sB + (t % GS) * GB_W;
#pragma unroll
        for (int kw = 0; kw < 32; kw += 8) {
            uint32_t af[4][4], bf[8][2];
#pragma unroll
            for (int mt = 0; mt < 4; mt++)
                ldsm4(af[mt], a + (wm + mt * 16 + lrA) * 36 + kw + lcA);
#pragma unroll
            for (int np = 0; np < 4; np++) {
                uint32_t tmp[4];
                ldsm4(tmp, b + (wn + np * 16 + lrB) * 36 + kw + lcB);
                bf[2 * np][0] = tmp[0];
                bf[2 * np][1] = tmp[1];
                bf[2 * np + 1][0] = tmp[2];
                bf[2 * np + 1][1] = tmp[3];
            }
#pragma unroll
            for (int mt = 0; mt < 4; mt++)
#pragma unroll
                for (int nt = 0; nt < 8; nt++) mma16(acc[mt][nt], af[mt], bf[nt]);
        }
    }
#pragma unroll
    for (int mt = 0; mt < 4; mt++)
#pragma unroll
        for (int nt = 0; nt < 8; nt++) {
            int row = m0 + wm + mt * 16 + g;
            int col = n0 + wn + nt * 8 + 2 * tg;
            if (half_out) {
                __half* C = (__half*)Cout;
                *(uint32_t*)(C + (size_t)row * DIM + col) =
                    h2u(acc[mt][nt][0] * out_scale, acc[mt][nt][1] * out_scale);
                *(uint32_t*)(C + (size_t)(row + 8) * DIM + col) =
                    h2u(acc[mt][nt][2] * out_scale, acc[mt][nt][3] * out_scale);
            } else {
                float* C = (float*)Cout;
                *(float2*)(C + (size_t)row * DIM + col) = make_float2(acc[mt][nt][0], acc[mt][nt][1]);
                *(float2*)(C + (size_t)(row + 8) * DIM + col) = make_float2(acc[mt][nt][2], acc[mt][nt][3]);
            }
        }
}

__global__ __launch_bounds__(256) void gemm_fp16(const __half* __restrict__ A,
                                                 const __half* __restrict__ WT,
                                                 void* __restrict__ Cout, int half_out,
                                                 float out_scale) {
    gemm_body(A, WT, Cout, half_out, out_scale, blockIdx.x, blockIdx.y);
}

// fused q/k/v projections: grid.z selects weight / destination / scale
__global__ __launch_bounds__(256) void gemm_qkv(const __half* __restrict__ A) {
    const int z = blockIdx.z;
    const __half* WT = g_w + (size_t)z * DIM * DIM;
    __half* dst = (z == 0) ? g_q : (z == 1) ? g_k : g_v;
    float sc = (z == 0) ? QSCALE : 1.0f;
    gemm_body(A, WT, dst, 1, sc, blockIdx.x, blockIdx.y);
}

// =====================================================================
// Pass A: R = 1 / sum_h 2^(q.k)   (q pre-scaled by scale*log2e)
// fp16 MMA with fp16 accumulator (C frags feed h2exp2 directly).
// =====================================================================
#define ZT_W (128 * 36)
#define Z_SMEM (4 * ZT_W * 4)

__global__ __launch_bounds__(256) void attn_z() {
    extern __shared__ uint32_t smu[];
    uint32_t* sQ = smu;
    uint32_t* sK = smu + 2 * ZT_W;
    const int tid = threadIdx.x;
    const int b = blockIdx.z, qt = blockIdx.y * 128, kt = blockIdx.x * 128;
    const int w = tid >> 5, lane = tid & 31, g = lane >> 2, tg = lane & 3;
    const int wm = (w >> 2) * 64, wn = (w & 3) * 32;
    const int lrA = (lane & 7) + ((lane >> 3) & 1) * 8, lcA = (lane >> 4) * 4;
    const int lrB = (lane & 7) + (lane >> 4) * 8, lcB = ((lane >> 3) & 1) * 4;

    const __half* qb = g_q + (size_t)(b * SEQ + qt) * DIM;
    const __half* kb = g_k + (size_t)(b * SEQ + kt) * DIM;

    auto load_head = [&](int st, int h) {
        uint32_t* q = sQ + st * ZT_W;
        uint32_t* k = sK + st * ZT_W;
#pragma unroll
        for (int i = 0; i < 4; i++) {
            int c = tid + 256 * i;
            int r = c >> 3, cw = (c & 7) * 4;
            cpa16(q + r * 36 + cw, qb + (size_t)r * DIM + h * HD + cw * 2);
            cpa16(k + r * 36 + cw, kb + (size_t)r * DIM + h * HD + cw * 2);
        }
    };

    float zacc[4][4][4]{};
    load_head(0, 0);
    cp_commit();

    for (int h = 0; h < NH; h++) {
        cp_wait<0>();
        __syncthreads();
        if (h + 1 < NH) load_head((h + 1) & 1, h + 1);
        cp_commit();
        const uint32_t* q = sQ + (h & 1) * ZT_W;
        const uint32_t* k = sK + (h & 1) * ZT_W;

        uint32_t sacc[4][4][2]{};  // fp16 accumulators (half2 row g / row g+8)
#pragma unroll
        for (int kw = 0; kw < 32; kw += 8) {
            uint32_t af[4][4], bf[4][2];
#pragma unroll
            for (int mt = 0; mt < 4; mt++)
                ldsm4(af[mt], q + (wm + mt * 16 + lrA) * 36 + kw + lcA);
#pragma unroll
            for (int np = 0; np < 2; np++) {
                uint32_t tmp[4];
                ldsm4(tmp, k + (wn + np * 16 + lrB) * 36 + kw + lcB);
                bf[2 * np][0] = tmp[0];
                bf[2 * np][1] = tmp[1];
                bf[2 * np + 1][0] = tmp[2];
                bf[2 * np + 1][1] = tmp[3];
            }
#pragma unroll
            for (int mt = 0; mt < 4; mt++)
#pragma unroll
                for (int nt = 0; nt < 4; nt++) mma16h(sacc[mt][nt], af[mt], bf[nt]);
        }
        // zacc += 2^sacc : C frags are already half2 -> h2exp2 directly
#pragma unroll
        for (int i = 0; i < 4; i++)
#pragma unroll
            for (int j = 0; j < 4; j++) {
                float2 e0 = __half22float2(h2exp2(*(__half2*)&sacc[i][j][0]));
                float2 e1 = __half22float2(h2exp2(*(__half2*)&sacc[i][j][1]));
                zacc[i][j][0] += e0.x;
                zacc[i][j][1] += e0.y;
                zacc[i][j][2] += e1.x;
                zacc[i][j][3] += e1.y;
            }
    }
#pragma unroll
    for (int mt = 0; mt < 4; mt++)
#pragma unroll
        for (int nt = 0; nt < 4; nt++) {
            int row = qt + wm + mt * 16 + g;
            int col = kt + wn + nt * 8 + 2 * tg;
            __half* rp = g_r + ((size_t)b * SEQ + row) * SEQ + col;
            *(uint32_t*)rp = h2u(1.f / zacc[mt][nt][0], 1.f / zacc[mt][nt][1]);
            *(uint32_t*)(rp + (size_t)8 * SEQ) = h2u(1.f / zacc[mt][nt][2], 1.f / zacc[mt][nt][3]);
        }
}

// =====================================================================
// Pass B: ctx = sum_k 2^(q.k) * R * V   (GEMM1 fp16-acc, fragment reuse)
// == R14 structure (proven fastest) ==
// =====================================================================
#define CQ_W (128 * 36)
#define CVT_W (64 * 68)
#define CR_W (128 * 68)
#define C_SMEM ((3 * CQ_W + 2 * CVT_W + 2 * CR_W) * 4)

__global__ __launch_bounds__(256) void attn_ctx() {
    extern __shared__ uint32_t smu[];
    uint32_t* sQ = smu;
    uint32_t* sK = smu + CQ_W;
    uint32_t* sV = smu + 3 * CQ_W;
    uint32_t* sR = smu + 3 * CQ_W + 2 * CVT_W;

    const int tid = threadIdx.x;
    const int b = blockIdx.z, h = blockIdx.x, qt = blockIdx.y * 128;
    const int w = tid >> 5, lane = tid & 31, g = lane >> 2, tg = lane & 3;
    const int wm = (w >> 2) * 64, wn = (w & 3) * 32;
    const int lrA = (lane & 7) + ((lane >> 3) & 1) * 8, lcA = (lane >> 4) * 4;
    const int lrB = (lane & 7) + (lane >> 4) * 8, lcB = ((lane >> 3) & 1) * 4;

    const int NT = SEQ / 128;

    auto load_kvr = [&](int t) {
        int slot = t & 1;
        const __half* kb = g_k + (size_t)(b * SEQ + t * 128) * DIM + h * HD;
        uint32_t* kd = sK + slot * CQ_W;
#pragma unroll
        for (int i = 0; i < 4; i++) {
            int c = tid + 256 * i;
            int r = c >> 3, cw = (c & 7) * 4;
            cpa16(kd + r * 36 + cw, kb + (size_t)r * DIM + cw * 2);
        }
        const __half* vtb = g_vT + ((size_t)(b * NH + h) * HD) * SEQ + t * 128;
        uint32_t* vd = sV + slot * CVT_W;
#pragma unroll
        for (int i = 0; i < 4; i++) {
            int c = tid + 256 * i;
            int r = c >> 4, cw = (c & 15) * 4;
            cpa16(vd + r * 68 + cw, vtb + (size_t)r * SEQ + cw * 2);
        }
        const __half* rb = g_r + ((size_t)b * SEQ + qt) * SEQ + t * 128;
        __half* rd = (__half*)(sR + slot * CR_W);
#pragma unroll
        for (int i = 0; i < 8; i++) {
            int c = tid + 256 * i;
            int r = c >> 4, ch = (c & 15) * 8;
            cpa16(rd + r * 136 + ch, rb + (size_t)r * SEQ + ch);
        }
    };

    {
        const __half* qb = g_q + (size_t)(b * SEQ + qt) * DIM + h * HD;
#pragma unroll
        for (int i = 0; i < 4; i++) {
            int c = tid + 256 * i;
            int r = c >> 3, cw = (c & 7) * 4;
            cpa16(sQ + r * 36 + cw, qb + (size_t)r * DIM + cw * 2);
        }
        load_kvr(0);
        cp_commit();
        load_kvr(1);
        cp_commit();
    }

    float cacc[4][8][4]{};

    for (int t = 0; t < NT; t++) {
        cp_wait<1>();
        __syncthreads();

        // GEMM1 (fp16 acc): S = Q @ K^T, log2-domain scores
        const uint32_t* kc = sK + (t & 1) * CQ_W;
        uint32_t sacc[4][4][2]{};
#pragma unroll
        for (int kw = 0; kw < 32; kw += 8) {
            uint32_t af[4][4], bf[4][2];
#pragma unroll
            for (int mt = 0; mt < 4; mt++)
                ldsm4(af[mt], sQ + (wm + mt * 16 + lrA) * 36 + kw + lcA);
#pragma unroll
            for (int np = 0; np < 2; np++) {
                uint32_t tmp[4];
                ldsm4(tmp, kc + (wn + np * 16 + lrB) * 36 + kw + lcB);
                bf[2 * np][0] = tmp[0];
                bf[2 * np][1] = tmp[1];
                bf[2 * np + 1][0] = tmp[2];
                bf[2 * np + 1][1] = tmp[3];
            }
#pragma unroll
            for (int mt = 0; mt < 4; mt++)
#pragma unroll
                for (int nt = 0; nt < 4; nt++) mma16h(sacc[mt][nt], af[mt], bf[nt]);
        }

        // Epilogue in registers: pa = 2^sacc * R  (A-fragments for GEMM2)
        const __half* rslot = (const __half*)(sR + (t & 1) * CR_W);
        uint32_t pa[4][2][4];
#pragma unroll
        for (int mt = 0; mt < 4; mt++)
#pragma unroll
            for (int kb = 0; kb < 2; kb++) {
                int row = wm + mt * 16 + g;
                int col = wn + (2 * kb) * 8 + 2 * tg;
                __half2 r0 = *(__half2*)(rslot + row * 136 + col);
                __half2 r1 = *(__half2*)(rslot + (row + 8) * 136 + col);
                __half2 r2 = *(__half2*)(rslot + row * 136 + col + 8);
                __half2 r3 = *(__half2*)(rslot + (row + 8) * 136 + col + 8);
                int lo = 2 * kb, hi = 2 * kb + 1;
                __half2 p0 = __hmul2(h2exp2(*(__half2*)&sacc[mt][lo][0]), r0);
                __half2 p1 = __hmul2(h2exp2(*(__half2*)&sacc[mt][lo][1]), r1);
                __half2 p2 = __hmul2(h2exp2(*(__half2*)&sacc[mt][hi][0]), r2);
                __half2 p3 = __hmul2(h2exp2(*(__half2*)&sacc[mt][hi][1]), r3);
                pa[mt][kb][0] = *(uint32_t*)&p0;
                pa[mt][kb][1] = *(uint32_t*)&p1;
                pa[mt][kb][2] = *(uint32_t*)&p2;
                pa[mt][kb][3] = *(uint32_t*)&p3;
            }

        // GEMM2 (fp32 acc): cacc += P_slice @ V_slice (64m x 64n x 32k per warp)
        const uint32_t* vslot = sV + (t & 1) * CVT_W;
        const int kwBase = wn >> 1;
#pragma unroll
        for (int kb = 0; kb < 2; kb++) {
            uint32_t bf[8][2];
#pragma unroll
            for (int np = 0; np < 4; np++) {
                uint32_t tmp[4];
                ldsm4(tmp, vslot + (np * 16 + lrB) * 68 + kwBase + kb * 8 + lcB);
                bf[2 * np][0] = tmp[0];
                bf[2 * np][1] = tmp[1];
                bf[2 * np + 1][0] = tmp[2];
                bf[2 * np + 1][1] = tmp[3];
            }
#pragma unroll
            for (int mt = 0; mt < 4; mt++)
#pragma unroll
                for (int nt = 0; nt < 8; nt++) mma16(cacc[mt][nt], pa[mt][kb], bf[nt]);
        }
        __syncthreads();

        if (t + 2 < NT) load_kvr(t + 2);
        cp_commit();
    }

    // 4-way k-slice reduction via sR (free now)
    float* red = (float*)sR;
    const int ks = w & 3, mg = w >> 2;
    float* rbase = red + mg * 64 * 68;
#pragma unroll
    for (int s = 1; s < 4; s++) {
        if (ks == s) {
#pragma unroll
            for (int mt = 0; mt < 4; mt++)
#pragma unroll
                for (int nt = 0; nt < 8; nt++) {
                    int row = mt * 16 + g;
                    int col = nt * 8 + 2 * tg;
                    if (s == 1) {
                        *(float2*)&rbase[row * 68 + col] = make_float2(cacc[mt][nt][0], cacc[mt][nt][1]);
                        *(float2*)&rbase[(row + 8) * 68 + col] = make_float2(cacc[mt][nt][2], cacc[mt][nt][3]);
                    } else {
                        float2 a0 = *(float2*)&rbase[row * 68 + col];
                        float2 a1 = *(float2*)&rbase[(row + 8) * 68 + col];
                        a0.x += cacc[mt][nt][0];
                        a0.y += cacc[mt][nt][1];
                        a1.x += cacc[mt][nt][2];
                        a1.y += cacc[mt][nt][3];
                        *(float2*)&rbase[row * 68 + col] = a0;
                        *(float2*)&rbase[(row + 8) * 68 + col] = a1;
                    }
                }
        }
        __syncthreads();
    }
    if (ks == 0) {
        __half* cb = g_ctx + (size_t)(b * SEQ + qt) * DIM + h * HD;
#pragma unroll
        for (int mt = 0; mt < 4; mt++)
#pragma unroll
            for (int nt = 0; nt < 8; nt++) {
                int row = mt * 16 + g;
                int col = nt * 8 + 2 * tg;
                float2 o0 = *(float2*)&rbase[row * 68 + col];
                float2 o1 = *(float2*)&rbase[(row + 8) * 68 + col];
                *(uint32_t*)(cb + (size_t)(wm + row) * DIM + col) =
                    h2u(o0.x + cacc[mt][nt][0], o0.y + cacc[mt][nt][1]);
                *(uint32_t*)(cb + (size_t)(wm + row + 8) * DIM + col) =
                    h2u(o1.x + cacc[mt][nt][2], o1.y + cacc[mt][nt][3]);
            }
    }
}

// =====================================================================
extern "C" void kernel_launch(void* const* d_in, const int* in_sizes, int n_in,
                              void* d_out, int out_size) {
    const float* x = (const float*)d_in[0];
    const float* wq = (const float*)d_in[1];
    const float* wk = (const float*)d_in[2];
    const float* wv = (const float*)d_in[3];
    const float* wo = (const float*)d_in[4];
    float* out = (float*)d_out;

    __half *ctx, *xr, *wr;
    cudaGetSymbolAddress((void**)&ctx, g_ctx);
    cudaGetSymbolAddress((void**)&xr, g_x);
    cudaGetSymbolAddress((void**)&wr, g_w);

    static int attr_done = 0;
    if (!attr_done) {
        cudaFuncSetAttribute(gemm_fp16, cudaFuncAttributeMaxDynamicSharedMemorySize, G_SMEM);
        cudaFuncSetAttribute(gemm_qkv, cudaFuncAttributeMaxDynamicSharedMemorySize, G_SMEM);
        cudaFuncSetAttribute(attn_z, cudaFuncAttributeMaxDynamicSharedMemorySize, Z_SMEM);
        cudaFuncSetAttribute(attn_ctx, cudaFuncAttributeMaxDynamicSharedMemorySize, C_SMEM);
        attr_done = 1;
    }

    round_all<<<dim3(1024, 1, 6), 256>>>(x, wq, wk, wv, wo);

    gemm_qkv<<<dim3(DIM / 256, MTOT / 128, 3), 256, G_SMEM>>>(xr);

    transpose_v64<<<dim3(SEQ / 64, DIM / 64, BATCH), 256>>>();

    attn_z<<<dim3(SEQ / 128, SEQ / 128, BATCH), 256, Z_SMEM>>>();

    attn_ctx<<<dim3(NH, SEQ / 128, BATCH), 256, C_SMEM>>>();

    gemm_fp16<<<dim3(DIM / 256, MTOT / 128), 256, G_SMEM>>>(ctx, wr + 3 * DIM * DIM, out, 0, 1.0f);
}